// round 4
// baseline (speedup 1.0000x reference)
#include <cuda_runtime.h>
#include <cuda_bf16.h>
#include <cstdint>

// Problem-fixed sizes (reference: B=262144, T=1048576)
#define MAXB 262144

// Scratch for state_h [B,64] — static device array (no allocations allowed)
__device__ float g_state[(size_t)MAXB * 64];

// 64-wide FMA helper: acc[j] += v * wrow[j], weights via vectorized uniform loads
__device__ __forceinline__ void fma64(float (&acc)[64], float v, const float* __restrict__ wrow) {
#pragma unroll
    for (int j4 = 0; j4 < 16; j4++) {
        float4 w = __ldg(reinterpret_cast<const float4*>(wrow) + j4);
        acc[4 * j4 + 0] = fmaf(v, w.x, acc[4 * j4 + 0]);
        acc[4 * j4 + 1] = fmaf(v, w.y, acc[4 * j4 + 1]);
        acc[4 * j4 + 2] = fmaf(v, w.z, acc[4 * j4 + 2]);
        acc[4 * j4 + 3] = fmaf(v, w.w, acc[4 * j4 + 3]);
    }
}

__device__ __forceinline__ void init64(float (&acc)[64], const float* __restrict__ b) {
#pragma unroll
    for (int j4 = 0; j4 < 16; j4++) {
        float4 w = __ldg(reinterpret_cast<const float4*>(b) + j4);
        acc[4 * j4 + 0] = w.x; acc[4 * j4 + 1] = w.y;
        acc[4 * j4 + 2] = w.z; acc[4 * j4 + 3] = w.w;
    }
}

// ===================== Kernel A: state encoder + values =====================
// One thread per sample. 32 threads/block; per-thread x[224] staged in smem
// (stride 225 -> conflict-free; 32*225*4 = 28.8 KB < 48 KB static limit).
#define BA 32

__global__ void __launch_bounds__(BA) state_kernel(
    const int*   __restrict__ hand_ids,      // [B,13]
    const float* __restrict__ dense_state,   // [B,107]
    const float* __restrict__ emb_table,     // [53,32]
    const float* __restrict__ ln1_g, const float* __restrict__ ln1_b,
    const float* __restrict__ W_card, const float* __restrict__ b_card,  // [416,64]
    const float* __restrict__ W_lp,   const float* __restrict__ b_lp,    // [52,64]
    const float* __restrict__ W_sn,   const float* __restrict__ b_sn,    // [52,64]
    const float* __restrict__ W_ct,   const float* __restrict__ b_ct,    // [3,32]
    const float* __restrict__ W_sp,   const float* __restrict__ b_sp,    // [224,64]
    const float* __restrict__ ln2_g,  const float* __restrict__ ln2_b,
    const float* __restrict__ Wv1,    const float* __restrict__ bv1,     // [64,64]
    const float* __restrict__ Wv2,    const float* __restrict__ bv2,     // [64,1]
    float* __restrict__ out_values,   // d_out + T
    int B)
{
    __shared__ float xs[BA * 225];
    int b = blockIdx.x * BA + threadIdx.x;
    if (b >= B) return;
    float* x = xs + threadIdx.x * 225;

    float acc[64];

    // ---- card embedding layer: e = relu(LN(emb[hand_ids]).flat @ W_card + b_card)
    init64(acc, b_card);
    const int* hid = hand_ids + (size_t)b * 13;
    for (int c = 0; c < 13; c++) {
        int id = __ldg(hid + c);
        if ((unsigned)id > 52u) id = 52;   // where(id<0, PAD) + safety clamp
        const float* er = emb_table + id * 32;
        float s = 0.f, s2 = 0.f;
#pragma unroll
        for (int d4 = 0; d4 < 8; d4++) {
            float4 v = __ldg(reinterpret_cast<const float4*>(er) + d4);
            s  += v.x + v.y + v.z + v.w;
            s2 += v.x * v.x + v.y * v.y + v.z * v.z + v.w * v.w;
        }
        float m = s * (1.f / 32.f);
        float r = rsqrtf(s2 * (1.f / 32.f) - m * m + 1e-5f);
        for (int d = 0; d < 32; d++) {
            float v = (__ldg(er + d) - m) * r * __ldg(ln1_g + d) + __ldg(ln1_b + d);
            fma64(acc, v, W_card + (c * 32 + d) * 64);
        }
    }
#pragma unroll
    for (int j = 0; j < 64; j++) x[j] = fmaxf(acc[j], 0.f);

    // ---- lp = relu(ds[0:52] @ W_lp + b_lp)
    const float* ds = dense_state + (size_t)b * 107;
    init64(acc, b_lp);
    for (int i = 0; i < 52; i++) fma64(acc, __ldg(ds + i), W_lp + i * 64);
#pragma unroll
    for (int j = 0; j < 64; j++) x[64 + j] = fmaxf(acc[j], 0.f);

    // ---- sn = relu(ds[52:104] @ W_sn + b_sn)
    init64(acc, b_sn);
    for (int i = 0; i < 52; i++) fma64(acc, __ldg(ds + 52 + i), W_sn + i * 64);
#pragma unroll
    for (int j = 0; j < 64; j++) x[128 + j] = fmaxf(acc[j], 0.f);

    // ---- ct = relu(ds[104:107] @ W_ct + b_ct)   (32 wide)
    {
        float a32[32];
#pragma unroll
        for (int j4 = 0; j4 < 8; j4++) {
            float4 w = __ldg(reinterpret_cast<const float4*>(b_ct) + j4);
            a32[4 * j4 + 0] = w.x; a32[4 * j4 + 1] = w.y;
            a32[4 * j4 + 2] = w.z; a32[4 * j4 + 3] = w.w;
        }
        for (int i = 0; i < 3; i++) {
            float v = __ldg(ds + 104 + i);
            const float* wr = W_ct + i * 32;
#pragma unroll
            for (int j4 = 0; j4 < 8; j4++) {
                float4 w = __ldg(reinterpret_cast<const float4*>(wr) + j4);
                a32[4 * j4 + 0] = fmaf(v, w.x, a32[4 * j4 + 0]);
                a32[4 * j4 + 1] = fmaf(v, w.y, a32[4 * j4 + 1]);
                a32[4 * j4 + 2] = fmaf(v, w.z, a32[4 * j4 + 2]);
                a32[4 * j4 + 3] = fmaf(v, w.w, a32[4 * j4 + 3]);
            }
        }
#pragma unroll
        for (int j = 0; j < 32; j++) x[192 + j] = fmaxf(a32[j], 0.f);
    }

    // ---- sp = LN(relu(x @ W_sp + b_sp))
    init64(acc, b_sp);
    for (int i = 0; i < 224; i++) fma64(acc, x[i], W_sp + i * 64);
    float s = 0.f, s2 = 0.f;
#pragma unroll
    for (int j = 0; j < 64; j++) {
        float v = fmaxf(acc[j], 0.f);
        acc[j] = v; s += v; s2 += v * v;
    }
    float m = s * (1.f / 64.f);
    float r = rsqrtf(s2 * (1.f / 64.f) - m * m + 1e-5f);
#pragma unroll
    for (int j = 0; j < 64; j++)
        acc[j] = (acc[j] - m) * r * __ldg(ln2_g + j) + __ldg(ln2_b + j);

    // write state_h + stash for value head
    float* sh = g_state + (size_t)b * 64;
#pragma unroll
    for (int j4 = 0; j4 < 16; j4++) {
        reinterpret_cast<float4*>(sh)[j4] =
            make_float4(acc[4 * j4], acc[4 * j4 + 1], acc[4 * j4 + 2], acc[4 * j4 + 3]);
        x[4 * j4]     = acc[4 * j4];
        x[4 * j4 + 1] = acc[4 * j4 + 1];
        x[4 * j4 + 2] = acc[4 * j4 + 2];
        x[4 * j4 + 3] = acc[4 * j4 + 3];
    }

    // ---- value head: v = relu(h @ Wv1 + bv1) @ Wv2 + bv2
    init64(acc, bv1);
    for (int i = 0; i < 64; i++) fma64(acc, x[i], Wv1 + i * 64);
    float val = __ldg(bv2);
#pragma unroll
    for (int j = 0; j < 64; j++) val = fmaf(fmaxf(acc[j], 0.f), __ldg(Wv2 + j), val);
    out_values[b] = val;
}

// ===================== Kernel B: action encoder + logits =====================
// One thread per action; all staging in registers (unroll-constant indexing).
#define BB 128

__global__ void __launch_bounds__(BB) action_kernel(
    const float* __restrict__ action_feats,  // [T,53]
    const int*   __restrict__ segment_ids,   // [T]
    const float* __restrict__ Wa1, const float* __restrict__ ba1,  // [53,64]
    const float* __restrict__ Wa2, const float* __restrict__ ba2,  // [64,64]
    const float* __restrict__ Wp1, const float* __restrict__ bp1,  // [128,64]
    const float* __restrict__ Wp2, const float* __restrict__ bp2,  // [64,1]
    float* __restrict__ out_logits,
    int T)
{
    int t = blockIdx.x * BB + threadIdx.x;
    if (t >= T) return;

    const float* af = action_feats + (size_t)t * 53;
    int seg = __ldg(segment_ids + t);

    float acc[64];
    float stg[64];

    // a = relu(af @ Wa1 + ba1)
    init64(acc, ba1);
#pragma unroll 4
    for (int i = 0; i < 53; i++) fma64(acc, __ldg(af + i), Wa1 + i * 64);
#pragma unroll
    for (int j = 0; j < 64; j++) stg[j] = fmaxf(acc[j], 0.f);

    // aenc = relu(a @ Wa2 + ba2)
    init64(acc, ba2);
#pragma unroll 4
    for (int i = 0; i < 64; i++) fma64(acc, stg[i], Wa2 + i * 64);
#pragma unroll
    for (int j = 0; j < 64; j++) stg[j] = fmaxf(acc[j], 0.f);

    // joint = [state_h[seg], aenc];  p1 = relu(joint @ Wp1 + bp1)
    init64(acc, bp1);
    const float* sh = g_state + (size_t)seg * 64;
#pragma unroll 4
    for (int i = 0; i < 64; i++) fma64(acc, __ldg(sh + i), Wp1 + i * 64);
#pragma unroll 4
    for (int i = 0; i < 64; i++) fma64(acc, stg[i], Wp1 + (64 + i) * 64);

    float logit = __ldg(bp2);
#pragma unroll
    for (int j = 0; j < 64; j++) logit = fmaf(fmaxf(acc[j], 0.f), __ldg(Wp2 + j), logit);
    out_logits[t] = logit;
}

// ===================== launch =====================
extern "C" void kernel_launch(void* const* d_in, const int* in_sizes, int n_in,
                              void* d_out, int out_size) {
    const int*   hand_ids     = (const int*)  d_in[0];
    const float* dense_state  = (const float*)d_in[1];
    const float* action_feats = (const float*)d_in[2];
    const int*   segment_ids  = (const int*)  d_in[3];
    const float* emb_table    = (const float*)d_in[4];
    const float* ln1_g        = (const float*)d_in[5];
    const float* ln1_b        = (const float*)d_in[6];
    const float* W_card       = (const float*)d_in[7];
    const float* b_card       = (const float*)d_in[8];
    const float* W_lp         = (const float*)d_in[9];
    const float* b_lp         = (const float*)d_in[10];
    const float* W_sn         = (const float*)d_in[11];
    const float* b_sn         = (const float*)d_in[12];
    const float* W_ct         = (const float*)d_in[13];
    const float* b_ct         = (const float*)d_in[14];
    const float* W_sp         = (const float*)d_in[15];
    const float* b_sp         = (const float*)d_in[16];
    const float* ln2_g        = (const float*)d_in[17];
    const float* ln2_b        = (const float*)d_in[18];
    const float* Wa1          = (const float*)d_in[19];
    const float* ba1          = (const float*)d_in[20];
    const float* Wa2          = (const float*)d_in[21];
    const float* ba2          = (const float*)d_in[22];
    const float* Wp1          = (const float*)d_in[23];
    const float* bp1          = (const float*)d_in[24];
    const float* Wp2          = (const float*)d_in[25];
    const float* bp2          = (const float*)d_in[26];
    const float* Wv1          = (const float*)d_in[27];
    const float* bv1          = (const float*)d_in[28];
    const float* Wv2          = (const float*)d_in[29];
    const float* bv2          = (const float*)d_in[30];

    int B = in_sizes[0] / 13;
    int T = in_sizes[3];
    float* out = (float*)d_out;   // layout: logits[T] then values[B]

    state_kernel<<<(B + BA - 1) / BA, BA>>>(
        hand_ids, dense_state, emb_table, ln1_g, ln1_b,
        W_card, b_card, W_lp, b_lp, W_sn, b_sn, W_ct, b_ct,
        W_sp, b_sp, ln2_g, ln2_b, Wv1, bv1, Wv2, bv2,
        out + (size_t)T, B);

    action_kernel<<<(T + BB - 1) / BB, BB>>>(
        action_feats, segment_ids, Wa1, ba1, Wa2, ba2,
        Wp1, bp1, Wp2, bp2, out, T);
}

// round 5
// speedup vs baseline: 1.2229x; 1.2229x over previous
#include <cuda_runtime.h>
#include <cuda_bf16.h>
#include <cstdint>

// Problem-fixed sizes (reference: B=262144, T=1048576)
#define MAXB 262144

// Scratch for state_h [B,64] — static device array (no allocations allowed)
__device__ float g_state[(size_t)MAXB * 64];

typedef unsigned long long u64t;

// ---- packed f32x2 helpers (Blackwell FFMA2 path, PTX-only) ----
__device__ __forceinline__ u64t pk2(float lo, float hi) {
    u64t r; asm("mov.b64 %0, {%1, %2};" : "=l"(r) : "f"(lo), "f"(hi)); return r;
}
__device__ __forceinline__ void upk2(u64t p, float& lo, float& hi) {
    asm("mov.b64 {%0, %1}, %2;" : "=f"(lo), "=f"(hi) : "l"(p));
}
__device__ __forceinline__ void ffma2(u64t& d, u64t a, u64t b) {
    asm("fma.rn.f32x2 %0, %1, %2, %0;" : "+l"(d) : "l"(a), "l"(b));
}

// 64-wide packed accumulate: acc[32] pairs (outputs 2k,2k+1), vv=(v,v)
__device__ __forceinline__ void fma64p(u64t (&acc)[32], u64t vv, const float* __restrict__ wrow) {
    const ulonglong2* wq = reinterpret_cast<const ulonglong2*>(wrow);
#pragma unroll
    for (int k = 0; k < 16; k++) {
        ulonglong2 q = __ldg(wq + k);
        ffma2(acc[2 * k + 0], vv, q.x);
        ffma2(acc[2 * k + 1], vv, q.y);
    }
}
__device__ __forceinline__ void init64p(u64t (&acc)[32], const float* __restrict__ b) {
    const ulonglong2* bq = reinterpret_cast<const ulonglong2*>(b);
#pragma unroll
    for (int k = 0; k < 16; k++) {
        ulonglong2 q = __ldg(bq + k);
        acc[2 * k + 0] = q.x; acc[2 * k + 1] = q.y;
    }
}

// ===================== Kernel A: state encoder + values =====================
// One thread per sample, 32 threads/block. x[224] staged in smem (stride 225,
// conflict-free). LN'd embedding table precomputed per block in smem.
#define BA 32

__global__ void __launch_bounds__(BA) state_kernel(
    const int*   __restrict__ hand_ids,
    const float* __restrict__ dense_state,
    const float* __restrict__ emb_table,
    const float* __restrict__ ln1_g, const float* __restrict__ ln1_b,
    const float* __restrict__ W_card, const float* __restrict__ b_card,
    const float* __restrict__ W_lp,   const float* __restrict__ b_lp,
    const float* __restrict__ W_sn,   const float* __restrict__ b_sn,
    const float* __restrict__ W_ct,   const float* __restrict__ b_ct,
    const float* __restrict__ W_sp,   const float* __restrict__ b_sp,
    const float* __restrict__ ln2_g,  const float* __restrict__ ln2_b,
    const float* __restrict__ Wv1,    const float* __restrict__ bv1,
    const float* __restrict__ Wv2,    const float* __restrict__ bv2,
    float* __restrict__ out_values,
    int B)
{
    __shared__ float xs[BA * 225];        // 28.8 KB
    __shared__ float lnemb[53 * 33];      // 7.0 KB  (padded stride 33)

    int tid = threadIdx.x;

    // ---- block-level precompute: LN'd embedding table ----
    for (int r = tid; r < 53; r += BA) {
        const float4* e4 = reinterpret_cast<const float4*>(emb_table + r * 32);
        float vals[32];
        float s = 0.f, s2 = 0.f;
#pragma unroll
        for (int k = 0; k < 8; k++) {
            float4 f = __ldg(e4 + k);
            vals[4 * k + 0] = f.x; vals[4 * k + 1] = f.y;
            vals[4 * k + 2] = f.z; vals[4 * k + 3] = f.w;
            s  += f.x + f.y + f.z + f.w;
            s2 += f.x * f.x + f.y * f.y + f.z * f.z + f.w * f.w;
        }
        float m = s * (1.f / 32.f);
        float rinv = rsqrtf(s2 * (1.f / 32.f) - m * m + 1e-5f);
#pragma unroll
        for (int d = 0; d < 32; d++)
            lnemb[r * 33 + d] = (vals[d] - m) * rinv * __ldg(ln1_g + d) + __ldg(ln1_b + d);
    }
    __syncthreads();

    int b = blockIdx.x * BA + tid;
    if (b >= B) return;
    float* x = xs + tid * 225;

    u64t acc[32];

    // ---- card layer: e = relu(LN(emb[ids]).flat @ W_card + b_card)
    init64p(acc, b_card);
    const int* hid = hand_ids + (size_t)b * 13;
    for (int c = 0; c < 13; c++) {
        int id = __ldg(hid + c);
        if ((unsigned)id > 52u) id = 52;
        const float* er = lnemb + id * 33;
        for (int d = 0; d < 32; d++) {
            float v = er[d];
            fma64p(acc, pk2(v, v), W_card + (c * 32 + d) * 64);
        }
    }
#pragma unroll
    for (int k = 0; k < 32; k++) {
        float a0, a1; upk2(acc[k], a0, a1);
        x[2 * k] = fmaxf(a0, 0.f); x[2 * k + 1] = fmaxf(a1, 0.f);
    }

    // ---- lp = relu(ds[0:52] @ W_lp + b_lp)
    const float* ds = dense_state + (size_t)b * 107;
    init64p(acc, b_lp);
    for (int i = 0; i < 52; i++) { float v = __ldg(ds + i); fma64p(acc, pk2(v, v), W_lp + i * 64); }
#pragma unroll
    for (int k = 0; k < 32; k++) {
        float a0, a1; upk2(acc[k], a0, a1);
        x[64 + 2 * k] = fmaxf(a0, 0.f); x[64 + 2 * k + 1] = fmaxf(a1, 0.f);
    }

    // ---- sn = relu(ds[52:104] @ W_sn + b_sn)
    init64p(acc, b_sn);
    for (int i = 0; i < 52; i++) { float v = __ldg(ds + 52 + i); fma64p(acc, pk2(v, v), W_sn + i * 64); }
#pragma unroll
    for (int k = 0; k < 32; k++) {
        float a0, a1; upk2(acc[k], a0, a1);
        x[128 + 2 * k] = fmaxf(a0, 0.f); x[128 + 2 * k + 1] = fmaxf(a1, 0.f);
    }

    // ---- ct = relu(ds[104:107] @ W_ct + b_ct)   (32 outputs, 16 pairs)
    {
        u64t a16[16];
        const ulonglong2* bq = reinterpret_cast<const ulonglong2*>(b_ct);
#pragma unroll
        for (int k = 0; k < 8; k++) { ulonglong2 q = __ldg(bq + k); a16[2 * k] = q.x; a16[2 * k + 1] = q.y; }
        for (int i = 0; i < 3; i++) {
            float v = __ldg(ds + 104 + i);
            u64t vv = pk2(v, v);
            const ulonglong2* wq = reinterpret_cast<const ulonglong2*>(W_ct + i * 32);
#pragma unroll
            for (int k = 0; k < 8; k++) {
                ulonglong2 q = __ldg(wq + k);
                ffma2(a16[2 * k], vv, q.x); ffma2(a16[2 * k + 1], vv, q.y);
            }
        }
#pragma unroll
        for (int k = 0; k < 16; k++) {
            float a0, a1; upk2(a16[k], a0, a1);
            x[192 + 2 * k] = fmaxf(a0, 0.f); x[192 + 2 * k + 1] = fmaxf(a1, 0.f);
        }
    }

    // ---- sp = LN(relu(x @ W_sp + b_sp))
    init64p(acc, b_sp);
    for (int i = 0; i < 224; i++) { float v = x[i]; fma64p(acc, pk2(v, v), W_sp + i * 64); }
    float s = 0.f, s2 = 0.f;
    float h[64];
#pragma unroll
    for (int k = 0; k < 32; k++) {
        float a0, a1; upk2(acc[k], a0, a1);
        a0 = fmaxf(a0, 0.f); a1 = fmaxf(a1, 0.f);
        h[2 * k] = a0; h[2 * k + 1] = a1;
        s += a0 + a1; s2 += a0 * a0 + a1 * a1;
    }
    float m = s * (1.f / 64.f);
    float rinv = rsqrtf(s2 * (1.f / 64.f) - m * m + 1e-5f);
    float* sh = g_state + (size_t)b * 64;
#pragma unroll
    for (int j = 0; j < 64; j++) {
        float v = (h[j] - m) * rinv * __ldg(ln2_g + j) + __ldg(ln2_b + j);
        x[j] = v;
    }
#pragma unroll
    for (int j4 = 0; j4 < 16; j4++)
        reinterpret_cast<float4*>(sh)[j4] =
            make_float4(x[4 * j4], x[4 * j4 + 1], x[4 * j4 + 2], x[4 * j4 + 3]);

    // ---- value head
    init64p(acc, bv1);
    for (int i = 0; i < 64; i++) { float v = x[i]; fma64p(acc, pk2(v, v), Wv1 + i * 64); }
    float val = __ldg(bv2);
#pragma unroll
    for (int k = 0; k < 32; k++) {
        float a0, a1; upk2(acc[k], a0, a1);
        val = fmaf(fmaxf(a0, 0.f), __ldg(Wv2 + 2 * k), val);
        val = fmaf(fmaxf(a1, 0.f), __ldg(Wv2 + 2 * k + 1), val);
    }
    out_values[b] = val;
}

// ===================== Kernel B: action encoder + logits =====================
// 32 threads/block; each thread handles 2 actions; 32-output passes share
// weight loads across both actions (8 LDG.128 : 32 FFMA2 per row).
#define BB 32

__global__ void __launch_bounds__(BB) action_kernel(
    const float* __restrict__ action_feats,  // [T,53]
    const int*   __restrict__ segment_ids,   // [T]
    const float* __restrict__ Wa1, const float* __restrict__ ba1,  // [53,64]
    const float* __restrict__ Wa2, const float* __restrict__ ba2,  // [64,64]
    const float* __restrict__ Wp1, const float* __restrict__ bp1,  // [128,64]
    const float* __restrict__ Wp2, const float* __restrict__ bp2,  // [64,1]
    float* __restrict__ out_logits,
    int T)
{
    __shared__ float afbuf[64 * 53];      // 13.6 KB (coalesced-staged action feats)
    __shared__ float abuf[BB * 129];      // 16.5 KB (a: 2 actions x 64, pad 129)
    __shared__ float ebuf[BB * 129];      // 16.5 KB (aenc)

    int tid = threadIdx.x;
    long long base_t = (long long)blockIdx.x * 64;

    // stage action feats coalesced
    {
        const float* src = action_feats + base_t * 53;
        int n = (int)min((long long)64, (long long)T - base_t) * 53;
        for (int idx = tid; idx < n; idx += BB) afbuf[idx] = src[idx];
    }
    __syncthreads();

    int t0 = (int)base_t + 2 * tid;
    int t1 = t0 + 1;
    bool ok0 = t0 < T, ok1 = t1 < T;
    int s0 = ok0 ? __ldg(segment_ids + t0) : 0;
    int s1 = ok1 ? __ldg(segment_ids + t1) : 0;

    const float* A0 = afbuf + (2 * tid) * 53;
    const float* A1 = afbuf + (2 * tid + 1) * 53;
    float* arow = abuf + tid * 129;
    float* erow = ebuf + tid * 129;

    float logit0 = 0.f, logit1 = 0.f;

    // ================= layer 1: a = relu(af @ Wa1 + ba1) =================
#pragma unroll
    for (int p = 0; p < 2; p++) {
        u64t c0[16], c1[16];
        const ulonglong2* bq = reinterpret_cast<const ulonglong2*>(ba1 + 32 * p);
#pragma unroll
        for (int k = 0; k < 8; k++) {
            ulonglong2 q = __ldg(bq + k);
            c0[2 * k] = q.x; c0[2 * k + 1] = q.y;
            c1[2 * k] = q.x; c1[2 * k + 1] = q.y;
        }
        for (int i = 0; i < 53; i++) {
            float v0 = A0[i], v1 = A1[i];
            u64t vv0 = pk2(v0, v0), vv1 = pk2(v1, v1);
            const ulonglong2* wq = reinterpret_cast<const ulonglong2*>(Wa1 + i * 64 + 32 * p);
#pragma unroll
            for (int k = 0; k < 8; k++) {
                ulonglong2 q = __ldg(wq + k);
                ffma2(c0[2 * k], vv0, q.x); ffma2(c0[2 * k + 1], vv0, q.y);
                ffma2(c1[2 * k], vv1, q.x); ffma2(c1[2 * k + 1], vv1, q.y);
            }
        }
#pragma unroll
        for (int k = 0; k < 16; k++) {
            float a0, a1; upk2(c0[k], a0, a1);
            arow[32 * p + 2 * k] = fmaxf(a0, 0.f); arow[32 * p + 2 * k + 1] = fmaxf(a1, 0.f);
            upk2(c1[k], a0, a1);
            arow[64 + 32 * p + 2 * k] = fmaxf(a0, 0.f); arow[64 + 32 * p + 2 * k + 1] = fmaxf(a1, 0.f);
        }
    }

    // ================= layer 2: aenc = relu(a @ Wa2 + ba2) =================
#pragma unroll
    for (int p = 0; p < 2; p++) {
        u64t c0[16], c1[16];
        const ulonglong2* bq = reinterpret_cast<const ulonglong2*>(ba2 + 32 * p);
#pragma unroll
        for (int k = 0; k < 8; k++) {
            ulonglong2 q = __ldg(bq + k);
            c0[2 * k] = q.x; c0[2 * k + 1] = q.y;
            c1[2 * k] = q.x; c1[2 * k + 1] = q.y;
        }
        for (int i = 0; i < 64; i++) {
            float v0 = arow[i], v1 = arow[64 + i];
            u64t vv0 = pk2(v0, v0), vv1 = pk2(v1, v1);
            const ulonglong2* wq = reinterpret_cast<const ulonglong2*>(Wa2 + i * 64 + 32 * p);
#pragma unroll
            for (int k = 0; k < 8; k++) {
                ulonglong2 q = __ldg(wq + k);
                ffma2(c0[2 * k], vv0, q.x); ffma2(c0[2 * k + 1], vv0, q.y);
                ffma2(c1[2 * k], vv1, q.x); ffma2(c1[2 * k + 1], vv1, q.y);
            }
        }
#pragma unroll
        for (int k = 0; k < 16; k++) {
            float a0, a1; upk2(c0[k], a0, a1);
            erow[32 * p + 2 * k] = fmaxf(a0, 0.f); erow[32 * p + 2 * k + 1] = fmaxf(a1, 0.f);
            upk2(c1[k], a0, a1);
            erow[64 + 32 * p + 2 * k] = fmaxf(a0, 0.f); erow[64 + 32 * p + 2 * k + 1] = fmaxf(a1, 0.f);
        }
    }

    // ============ layer 3: relu([state_h, aenc] @ Wp1 + bp1) -> head ============
    const float4* S0 = reinterpret_cast<const float4*>(g_state + (size_t)s0 * 64);
    const float4* S1 = reinterpret_cast<const float4*>(g_state + (size_t)s1 * 64);
#pragma unroll
    for (int p = 0; p < 2; p++) {
        u64t c0[16], c1[16];
        const ulonglong2* bq = reinterpret_cast<const ulonglong2*>(bp1 + 32 * p);
#pragma unroll
        for (int k = 0; k < 8; k++) {
            ulonglong2 q = __ldg(bq + k);
            c0[2 * k] = q.x; c0[2 * k + 1] = q.y;
            c1[2 * k] = q.x; c1[2 * k + 1] = q.y;
        }
        // state part: rows 0..63
        for (int i4 = 0; i4 < 16; i4++) {
            float4 f0 = __ldg(S0 + i4);
            float4 f1 = __ldg(S1 + i4);
#pragma unroll
            for (int c = 0; c < 4; c++) {
                float v0 = (c == 0) ? f0.x : (c == 1) ? f0.y : (c == 2) ? f0.z : f0.w;
                float v1 = (c == 0) ? f1.x : (c == 1) ? f1.y : (c == 2) ? f1.z : f1.w;
                u64t vv0 = pk2(v0, v0), vv1 = pk2(v1, v1);
                const ulonglong2* wq =
                    reinterpret_cast<const ulonglong2*>(Wp1 + (i4 * 4 + c) * 64 + 32 * p);
#pragma unroll
                for (int k = 0; k < 8; k++) {
                    ulonglong2 q = __ldg(wq + k);
                    ffma2(c0[2 * k], vv0, q.x); ffma2(c0[2 * k + 1], vv0, q.y);
                    ffma2(c1[2 * k], vv1, q.x); ffma2(c1[2 * k + 1], vv1, q.y);
                }
            }
        }
        // aenc part: rows 64..127
        for (int i = 0; i < 64; i++) {
            float v0 = erow[i], v1 = erow[64 + i];
            u64t vv0 = pk2(v0, v0), vv1 = pk2(v1, v1);
            const ulonglong2* wq = reinterpret_cast<const ulonglong2*>(Wp1 + (64 + i) * 64 + 32 * p);
#pragma unroll
            for (int k = 0; k < 8; k++) {
                ulonglong2 q = __ldg(wq + k);
                ffma2(c0[2 * k], vv0, q.x); ffma2(c0[2 * k + 1], vv0, q.y);
                ffma2(c1[2 * k], vv1, q.x); ffma2(c1[2 * k + 1], vv1, q.y);
            }
        }
        // head partial: logit += relu(l3) . Wp2[32p..32p+31]
#pragma unroll
        for (int k = 0; k < 16; k++) {
            float w0 = __ldg(Wp2 + 32 * p + 2 * k);
            float w1 = __ldg(Wp2 + 32 * p + 2 * k + 1);
            float a0, a1; upk2(c0[k], a0, a1);
            logit0 = fmaf(fmaxf(a0, 0.f), w0, logit0);
            logit0 = fmaf(fmaxf(a1, 0.f), w1, logit0);
            upk2(c1[k], a0, a1);
            logit1 = fmaf(fmaxf(a0, 0.f), w0, logit1);
            logit1 = fmaf(fmaxf(a1, 0.f), w1, logit1);
        }
    }

    float bp = __ldg(bp2);
    if (ok0) out_logits[t0] = logit0 + bp;
    if (ok1) out_logits[t1] = logit1 + bp;
}

// ===================== launch =====================
extern "C" void kernel_launch(void* const* d_in, const int* in_sizes, int n_in,
                              void* d_out, int out_size) {
    const int*   hand_ids     = (const int*)  d_in[0];
    const float* dense_state  = (const float*)d_in[1];
    const float* action_feats = (const float*)d_in[2];
    const int*   segment_ids  = (const int*)  d_in[3];
    const float* emb_table    = (const float*)d_in[4];
    const float* ln1_g        = (const float*)d_in[5];
    const float* ln1_b        = (const float*)d_in[6];
    const float* W_card       = (const float*)d_in[7];
    const float* b_card       = (const float*)d_in[8];
    const float* W_lp         = (const float*)d_in[9];
    const float* b_lp         = (const float*)d_in[10];
    const float* W_sn         = (const float*)d_in[11];
    const float* b_sn         = (const float*)d_in[12];
    const float* W_ct         = (const float*)d_in[13];
    const float* b_ct         = (const float*)d_in[14];
    const float* W_sp         = (const float*)d_in[15];
    const float* b_sp         = (const float*)d_in[16];
    const float* ln2_g        = (const float*)d_in[17];
    const float* ln2_b        = (const float*)d_in[18];
    const float* Wa1          = (const float*)d_in[19];
    const float* ba1          = (const float*)d_in[20];
    const float* Wa2          = (const float*)d_in[21];
    const float* ba2          = (const float*)d_in[22];
    const float* Wp1          = (const float*)d_in[23];
    const float* bp1          = (const float*)d_in[24];
    const float* Wp2          = (const float*)d_in[25];
    const float* bp2          = (const float*)d_in[26];
    const float* Wv1          = (const float*)d_in[27];
    const float* bv1          = (const float*)d_in[28];
    const float* Wv2          = (const float*)d_in[29];
    const float* bv2          = (const float*)d_in[30];

    int B = in_sizes[0] / 13;
    int T = in_sizes[3];
    float* out = (float*)d_out;   // layout: logits[T] then values[B]

    state_kernel<<<(B + BA - 1) / BA, BA>>>(
        hand_ids, dense_state, emb_table, ln1_g, ln1_b,
        W_card, b_card, W_lp, b_lp, W_sn, b_sn, W_ct, b_ct,
        W_sp, b_sp, ln2_g, ln2_b, Wv1, bv1, Wv2, bv2,
        out + (size_t)T, B);

    action_kernel<<<(T + 63) / 64, BB>>>(
        action_feats, segment_ids, Wa1, ba1, Wa2, ba2,
        Wp1, bp1, Wp2, bp2, out, T);
}